// round 9
// baseline (speedup 1.0000x reference)
#include <cuda_runtime.h>
#include <cuda_bf16.h>

#define L 45
#define LP 48              // padded label count
#define SMAX 512
#define START_IDX 43
#define STOP_IDX 44
#define PF 4               // logit prefetch distance
#define NB 1024            // batch size (fixed for this problem)
#define LOG2E 1.4426950408889634f
#define LN2   0.6931471805599453f

__device__ __forceinline__ float ex2f(float x) {
    float r; asm("ex2.approx.ftz.f32 %0, %1;" : "=f"(r) : "f"(x)); return r;
}
__device__ __forceinline__ float lg2f(float x) {
    float r; asm("lg2.approx.ftz.f32 %0, %1;" : "=f"(r) : "f"(x)); return r;
}
__device__ __forceinline__ void fma2(unsigned long long& d,
                                     unsigned long long a, unsigned long long b) {
    asm("fma.rn.f32x2 %0, %1, %2, %0;" : "+l"(d) : "l"(a), "l"(b));
}
__device__ __forceinline__ void add2(unsigned long long& d, unsigned long long a) {
    asm("add.rn.f32x2 %0, %0, %1;" : "+l"(d) : "l"(a));
}
__device__ __forceinline__ unsigned long long pack2(float lo, float hi) {
    unsigned long long v;
    asm("mov.b64 %0, {%1, %2};" : "=l"(v) : "f"(lo), "f"(hi)); return v;
}
__device__ __forceinline__ float2 unpack2(unsigned long long v) {
    float2 f; asm("mov.b64 {%0, %1}, %2;" : "=f"(f.x), "=f"(f.y) : "l"(v)); return f;
}

// permutation of batch indices, sorted by descending length
__device__ int d_perm[NB];

// ---- pre-pass: bitonic sort of (len desc, idx) keys, one 1024-thread block ----
__global__ void sort_lens_kernel(const int* __restrict__ lens, int B) {
    __shared__ unsigned sk[NB];
    const int t = threadIdx.x;
    const int len = (t < B) ? lens[t] : 0;
    // ascending sort of (SMAX-len, idx)  ==  descending by len, idx tiebreak
    sk[t] = ((unsigned)(SMAX - len) << 12) | (unsigned)t;
    __syncthreads();
    for (int k = 2; k <= NB; k <<= 1) {
        for (int j = k >> 1; j > 0; j >>= 1) {
            const int ixj = t ^ j;
            if (ixj > t) {
                const unsigned a = sk[t], c = sk[ixj];
                const bool up = ((t & k) == 0);
                if (up ? (a > c) : (a < c)) { sk[t] = c; sk[ixj] = a; }
            }
            __syncthreads();
        }
    }
    d_perm[t] = (int)(sk[t] & 0xFFFu);
}

// ---- main kernel: 256 threads = 4 length-sorted batches ("pairs") ----
// pair q = warps 2q,2q+1 -> SMSP pairs {0,1},{2,3},{0,1},{2,3}: all four
// SMSPs loaded by construction. One plain __syncthreads per step; batches in
// a block have near-equal sorted lens, so running to lmax with branchless
// freeze costs ~nothing.
// Per pair, thread i = tid&63: i<45 e-producers (expT row in regs, packed
// f32x2 dot), i==45 dedicated scale-increment producer (copy of row 0; its
// lg2 runs in parallel with everyone's ex2).
// Recurrence (base-2, scaled-linear): s_i = sum_j expT[i,j]*e[j];
//   e'_i = s_i * 2^(lgt2_i - c2);  M2 += c2;  c2' = lg2(s_0)+lgt2_0-c2 (stale).
__global__ __launch_bounds__(256) void crf_fwd_kernel(
    const float* __restrict__ logits,      // [B, S, L]
    const int*   __restrict__ lens,        // [B]
    const float* __restrict__ trans,       // [L, L], trans[i*L+j]=score(j->i)
    float*       __restrict__ out)         // [B]
{
    const int pair = threadIdx.x >> 6;     // 0..3
    const int i    = threadIdx.x & 63;     // thread within pair
    const int b    = d_perm[blockIdx.x * 4 + pair];

    __shared__ __align__(16) float e_sm[4][2][LP];
    __shared__ float c_sm[4][2];
    __shared__ float m_sm[4];
    __shared__ int   len_sm[4];
    __shared__ float red_sm[4][LP];

    float (*e_s)[LP] = e_sm[pair];
    float* c_s = c_sm[pair];
    float* red = red_sm[pair];

    const bool is_e = (i < L);
    const bool is_c = (i == L);            // thread 45 of the pair
    const bool ld   = is_e | is_c;
    const int  lab  = is_e ? i : 0;

    if (i < LP) { e_s[0][i] = 0.f; e_s[1][i] = 0.f; }
    if (i == 0) { c_s[0] = 0.f; c_s[1] = 0.f; }

    // packed expT row in registers
    unsigned long long rowp[LP / 2];
#pragma unroll
    for (int m = 0; m < LP / 2; m++) rowp[m] = 0ull;
    if (ld) {
#pragma unroll
        for (int m = 0; m < LP / 2; m++) {
            const float x0 = __expf(trans[lab * L + 2 * m]);
            const float x1 = (2 * m + 1 < L) ? __expf(trans[lab * L + 2 * m + 1]) : 0.f;
            rowp[m] = pack2(x0, x1);
        }
    }

    const int len = lens[b];
    if (i == 0) len_sm[pair] = len;
    const float* lg = logits + (size_t)b * SMAX * L;

    // ---- t = 0 analytically: alpha0 = logit[0] + T[:, START] ----
    float a0v = 0.f;
    if (is_e) a0v = lg[i] + trans[i * L + START_IDX];
    if (i == 0) m_sm[pair] = a0v;
    __syncthreads();
    const int lmax = max(max(len_sm[0], len_sm[1]), max(len_sm[2], len_sm[3]));
    const float mu0 = m_sm[pair];
    float M2 = mu0 * LOG2E;                // running scale (base-2)
    float e_loc = ex2f((a0v - mu0) * LOG2E);
    if (is_e) e_s[1][i] = e_loc;

    // ---- prefetch logits (pre-scaled by log2e) ----
    float lgbuf[PF];
#pragma unroll
    for (int u = 0; u < PF; u++) {
        const int t = 1 + u;
        lgbuf[u] = (ld && t < len) ? lg[t * L + lab] * LOG2E : 0.f;
    }

#define STEP(tt, uu) do {                                                     \
        const int p_ = (tt) & 1;                                              \
        __syncthreads();                                                      \
        const bool act_ = ((tt) < len);                                       \
        const float lgt2_ = lgbuf[uu];                                        \
        { const int tn_ = (tt) + PF;                                          \
          lgbuf[uu] = (ld && tn_ < len) ? lg[tn_ * L + lab] * LOG2E : 0.f; }  \
        const float c2_ = c_s[p_ ^ 1];                                        \
        const ulonglong2* e2_ = (const ulonglong2*)(e_s[p_]);                 \
        unsigned long long ac_[8] = {0,0,0,0,0,0,0,0};                        \
        _Pragma("unroll")                                                     \
        for (int h_ = 0; h_ < LP / 4; h_++) {                                 \
            const ulonglong2 w_ = e2_[h_];                                    \
            fma2(ac_[(2 * h_)     & 7], rowp[2 * h_],     w_.x);              \
            fma2(ac_[(2 * h_ + 1) & 7], rowp[2 * h_ + 1], w_.y);              \
        }                                                                     \
        add2(ac_[0], ac_[4]); add2(ac_[1], ac_[5]);                           \
        add2(ac_[2], ac_[6]); add2(ac_[3], ac_[7]);                           \
        add2(ac_[0], ac_[2]); add2(ac_[1], ac_[3]);                           \
        add2(ac_[0], ac_[1]);                                                 \
        const float2 f_ = unpack2(ac_[0]);                                    \
        const float s_ = f_.x + f_.y;                                         \
        const float en_ = s_ * ex2f(lgt2_ - c2_);                             \
        if (is_e) {                                                           \
            e_loc = act_ ? en_ : e_loc;      /* FSEL, branchless freeze */    \
            e_s[p_ ^ 1][i] = e_loc;                                           \
        }                                                                     \
        if (is_c) c_s[p_] = act_ ? (lg2f(s_) + lgt2_ - c2_) : c2_;            \
        M2 += act_ ? c2_ : 0.f;                                               \
    } while (0)

    // main loop to lmax (~= len, sorted): full PF-chunks + tail
    int t = 1;
    for (; t + PF <= lmax; t += PF) {
        STEP(t + 0, 0);
        STEP(t + 1, 1);
        STEP(t + 2, 2);
        STEP(t + 3, 3);
    }
    if (t < lmax) { STEP(t, 0); t++; }
    if (t < lmax) { STEP(t, 1); t++; }
    if (t < lmax) { STEP(t, 2); }
#undef STEP

    // ---- epilogue: out[b] = LSE_i( alpha_i + T[STOP, i] ) ----
    if (is_e) red[i] = (M2 + lg2f(e_loc)) * LN2 + trans[STOP_IDX * L + i];
    __syncthreads();
    if (i == 0) {
        float m = red[0];
#pragma unroll
        for (int j = 1; j < L; j++) m = fmaxf(m, red[j]);
        float s = 0.f;
#pragma unroll
        for (int j = 0; j < L; j++) s += __expf(red[j] - m);
        out[b] = m + __logf(s);
    }
}

extern "C" void kernel_launch(void* const* d_in, const int* in_sizes, int n_in,
                              void* d_out, int out_size) {
    const float* logits = (const float*)d_in[0];   // [1024, 512, 45] f32
    const int*   lens   = (const int*)d_in[1];     // [1024] i32
    const float* trans  = (const float*)d_in[2];   // [45, 45] f32
    float* out = (float*)d_out;                    // [1024] f32

    const int B = in_sizes[1];                     // 1024
    sort_lens_kernel<<<1, NB>>>(lens, B);
    crf_fwd_kernel<<<B / 4, 256>>>(logits, lens, trans, out);
}

// round 11
// speedup vs baseline: 1.1194x; 1.1194x over previous
#include <cuda_runtime.h>
#include <cuda_bf16.h>

#define L 45
#define NS 48              // ull slots per e-buffer: 45 used (one per label) + pad
#define SMAX 512
#define START_IDX 43
#define STOP_IDX 44
#define PF 4               // logit prefetch distance (steps)
#define LOG2E 1.4426950408889634f
#define LN2   0.6931471805599453f
#define FULLM 0xFFFFFFFFu

typedef unsigned long long ull;

__device__ __forceinline__ float ex2f(float x) {
    float r; asm("ex2.approx.ftz.f32 %0, %1;" : "=f"(r) : "f"(x)); return r;
}
__device__ __forceinline__ float lg2f(float x) {
    float r; asm("lg2.approx.ftz.f32 %0, %1;" : "=f"(r) : "f"(x)); return r;
}
__device__ __forceinline__ void fma2(ull& d, ull a, ull b) {
    asm("fma.rn.f32x2 %0, %1, %2, %0;" : "+l"(d) : "l"(a), "l"(b));
}
__device__ __forceinline__ void add2(ull& d, ull a) {
    asm("add.rn.f32x2 %0, %0, %1;" : "+l"(d) : "l"(a));
}
__device__ __forceinline__ ull fma2n(ull a, ull b, ull c) {
    ull d; asm("fma.rn.f32x2 %0, %1, %2, %3;" : "=l"(d) : "l"(a), "l"(b), "l"(c));
    return d;
}
__device__ __forceinline__ ull pack2(float lo, float hi) {
    ull v; asm("mov.b64 %0, {%1, %2};" : "=l"(v) : "f"(lo), "f"(hi)); return v;
}
__device__ __forceinline__ float2 unpack2(ull v) {
    float2 f; asm("mov.b64 {%0, %1}, %2;" : "=f"(f.x), "=f"(f.y) : "l"(v)); return f;
}

// ONE BATCH PER WARP; 4 warps (4 independent batches) per 128-thread block so
// wid%4 loads all four SMSPs. NO block barriers -- warps never interact; per
// step a single __syncwarp orders the per-warp smem exchange.
// Lane k<=21 owns labels {2k, 2k+1}: its f32x2 accumulator pair IS (s_2k,
// s_2k+1) -- no cross-thread reduction. Lane 22 owns label 44 (lo half only).
// Lane 23 duplicates row 0 and produces the scale increment c (its lg2 runs
// in parallel with everyone's ex2). Lanes 24-31 idle.
// e-vector stored DUPLICATED (e_j, e_j) one ull slot per label so dots read
// broadcast ulonglong2 (LDS.128) straight into fma2.
// Recurrence (base-2, scaled-linear): s_i = sum_j expT[i,j]*e[j];
//   e'_i = s_i * 2^(lgt_i*log2e - c);  M2 += c;  c' = lg2(s_0)+lgt_0*log2e-c.
__global__ __launch_bounds__(128) void crf_fwd_kernel(
    const float* __restrict__ logits,      // [B, S, L]
    const int*   __restrict__ lens,        // [B]
    const float* __restrict__ trans,       // [L, L], trans[i*L+j]=score(j->i)
    float*       __restrict__ out,         // [B]
    int B)
{
    const int wid = threadIdx.x >> 5;
    const int k   = threadIdx.x & 31;
    const int b   = blockIdx.x * 4 + wid;
    if (b >= B) return;                    // warp-uniform

    __shared__ __align__(16) ull e_sm[4][2][NS];
    __shared__ ull negc_sm[4][2];
    ull (*e_s)[NS] = e_sm[wid];
    ull* negc_s = negc_sm[wid];

    const bool isC   = (k == 23);          // c-producer (row 0 duplicate)
    const bool hasLo = (k <= 22);
    const bool hasHi = (k <= 21);
    const bool ldLo  = hasLo | isC;
    const int  labLo = isC ? 0 : (hasLo ? 2 * k : 0);
    const int  labHi = hasHi ? 2 * k + 1 : 0;   // isC -> 0 (dup row 0)
    const bool enHi  = hasHi | isC;

    // packed expT rows: rowp[j] = (expT[labLo][j], expT[labHi][j])
    ull rowp[L];
#pragma unroll
    for (int j = 0; j < L; j++) {
        const float rl = ldLo ? __expf(trans[labLo * L + j]) : 0.f;
        const float rh = enHi ? __expf(trans[labHi * L + j]) : 0.f;
        rowp[j] = pack2(rl, rh);
    }

    const int len = lens[b];
    const float* lg = logits + (size_t)b * SMAX * L;
    const ull L2E2 = pack2(LOG2E, LOG2E);

    // ---- t = 0 analytically: alpha0 = logit[0] + T[:, START] ----
    const float a0lo = ldLo ? (lg[labLo] + trans[labLo * L + START_IDX]) : 0.f;
    const float a0hi = hasHi ? (lg[labHi] + trans[labHi * L + START_IDX]) : 0.f;
    const float mu0 = __shfl_sync(FULLM, a0lo, 0);
    float M2 = mu0 * LOG2E;                // running scale (base-2)
    float eLo = ex2f((a0lo - mu0) * LOG2E);
    float eHi = hasHi ? ex2f((a0hi - mu0) * LOG2E) : 0.f;
    if (hasHi) {                           // slots 2k, 2k+1 (STS.128)
        ((ulonglong2*)e_s[1])[k] = make_ulonglong2(pack2(eLo, eLo), pack2(eHi, eHi));
    } else if (k == 22) {                  // slot 44 (STS.64)
        e_s[1][44] = pack2(eLo, eLo);
    }
    if (isC) { negc_s[0] = 0ull; }

    // ---- prefetch logits (raw; scaled by log2e inside the step fma2) ----
    ull lgbuf[PF];
#pragma unroll
    for (int u = 0; u < PF; u++) {
        const int t = 1 + u;
        float lo = (ldLo && t < len) ? lg[t * L + labLo] : 0.f;
        float hi = (hasHi && t < len) ? lg[t * L + labHi] : 0.f;
        if (isC) hi = lo;
        lgbuf[u] = pack2(lo, hi);
    }

#define STEP(tt, uu) do {                                                     \
        const int p_ = (tt) & 1;                                              \
        __syncwarp();                                                         \
        const ull lgp_ = lgbuf[uu];                                           \
        { const int tn_ = (tt) + PF;                                          \
          float lo_ = (ldLo && tn_ < len) ? lg[tn_ * L + labLo] : 0.f;        \
          float hi_ = (hasHi && tn_ < len) ? lg[tn_ * L + labHi] : 0.f;       \
          if (isC) hi_ = lo_;                                                 \
          lgbuf[uu] = pack2(lo_, hi_); }                                      \
        const ull negc2_ = negc_s[p_ ^ 1];                                    \
        const ulonglong2* e2_ = (const ulonglong2*)(e_s[p_]);                 \
        ull ac_[4] = {0, 0, 0, 0};                                            \
        _Pragma("unroll")                                                     \
        for (int h_ = 0; h_ < 22; h_++) {                                     \
            const ulonglong2 w_ = e2_[h_];                                    \
            fma2(ac_[(2 * h_)     & 3], rowp[2 * h_],     w_.x);              \
            fma2(ac_[(2 * h_ + 1) & 3], rowp[2 * h_ + 1], w_.y);              \
        }                                                                     \
        fma2(ac_[0], rowp[44], e_s[p_][44]);                                  \
        add2(ac_[0], ac_[2]); add2(ac_[1], ac_[3]); add2(ac_[0], ac_[1]);     \
        const float2 s2_ = unpack2(ac_[0]);                                   \
        const ull x2_ = fma2n(lgp_, L2E2, negc2_);   /* lgt*log2e - c */      \
        const float2 xf_ = unpack2(x2_);                                      \
        eLo = s2_.x * ex2f(xf_.x);                                            \
        eHi = s2_.y * ex2f(xf_.y);                                            \
        if (hasHi) {                                                          \
            ((ulonglong2*)e_s[p_ ^ 1])[k] =                                   \
                make_ulonglong2(pack2(eLo, eLo), pack2(eHi, eHi));            \
        } else if (k == 22) {                                                 \
            e_s[p_ ^ 1][44] = pack2(eLo, eLo);                                \
        }                                                                     \
        if (isC) {                                                            \
            const float cn_ = lg2f(s2_.x) + xf_.x;                            \
            negc_s[p_] = pack2(-cn_, -cn_);                                   \
        }                                                                     \
        M2 -= unpack2(negc2_).x;                                              \
    } while (0)

    // main loop: per-warp (len uniform across lanes), full PF-chunks + tail
    int t = 1;
    for (; t + PF <= len; t += PF) {
        STEP(t + 0, 0);
        STEP(t + 1, 1);
        STEP(t + 2, 2);
        STEP(t + 3, 3);
    }
    if (t < len) { STEP(t, 0); t++; }
    if (t < len) { STEP(t, 1); t++; }
    if (t < len) { STEP(t, 2); }
#undef STEP

    // ---- epilogue: out[b] = LSE_i( alpha_i + T[STOP, i] ) ----
    // alpha_i = (M2 + lg2(e_i)) * ln2
    float vLo = -1e30f, vHi = -1e30f;
    if (hasLo) vLo = (M2 + lg2f(eLo)) * LN2 + trans[STOP_IDX * L + labLo];
    if (hasHi) vHi = (M2 + lg2f(eHi)) * LN2 + trans[STOP_IDX * L + labHi];
    float m = fmaxf(vLo, vHi);
#pragma unroll
    for (int off = 16; off; off >>= 1)
        m = fmaxf(m, __shfl_xor_sync(FULLM, m, off));
    float s = (hasLo ? ex2f((vLo - m) * LOG2E) : 0.f)
            + (hasHi ? ex2f((vHi - m) * LOG2E) : 0.f);
#pragma unroll
    for (int off = 16; off; off >>= 1)
        s += __shfl_xor_sync(FULLM, s, off);
    if (k == 0) out[b] = m + lg2f(s) * LN2;
}

extern "C" void kernel_launch(void* const* d_in, const int* in_sizes, int n_in,
                              void* d_out, int out_size) {
    const float* logits = (const float*)d_in[0];   // [1024, 512, 45] f32
    const int*   lens   = (const int*)d_in[1];     // [1024] i32
    const float* trans  = (const float*)d_in[2];   // [45, 45] f32
    float* out = (float*)d_out;                    // [1024] f32

    const int B = in_sizes[1];                     // 1024
    crf_fwd_kernel<<<(B + 3) / 4, 128>>>(logits, lens, trans, out, B);
}